// round 15
// baseline (speedup 1.0000x reference)
#include <cuda_runtime.h>
#include <cuda_bf16.h>
#include <math.h>
#include <stdint.h>

#define D       256
#define BN      4096
#define QN      65536
#define HALF    2048
#define TEMP_INV 10.0f

// ---- stage-1 mma.sync tiling: 128x128 tile, 256 thr, 3-stage pipeline ----
#define BM      128
#define BNT     128
#define KC      64
#define NKC     (D / KC)
#define PA      72                      // smem pitch (bf16): 144B rows, LDSM conflict-free
#define ABYTES  (BM * PA * 2)           // 18432
#define BBYTES  (BNT * PA * 2)          // 18432
#define STAGE_BYTES (ABYTES + BBYTES)   // 36864
#define SIM_SMEM    (3 * STAGE_BYTES)   // 110592 (2 CTAs/SM)

#define NSLOT   (QN / BNT)              // 512 partial-top2 slots per row
#define EPS     0.08f

// ---- stage-3 (plain bf16) tiling: 128x128 tiles, double-buffered, 2 CTAs/SM ----
#define LBN     128
#define LNCH    (HALF / LBN)            // 16 col chunks
#define LSTG    (2 * ABYTES)            // A + B chunk = 36864
#define LOSS_SMEM (2 * LSTG)            // 73728 (2 CTAs/SM)
#define LOSS_GRID (LNCH * (BN / BM))    // 512 CTAs

// ---- scratch (no allocations allowed) ----
__device__ __nv_bfloat16 g_emb_bf[BN * D];
__device__ __nv_bfloat16 g_queue_bf[QN * D];
__device__ __nv_bfloat16 g_preds_bf[BN * D];
__device__ __nv_bfloat16 g_nn_bf[BN * D];
__device__ float g_p1v[BN * NSLOT];
__device__ int   g_p1i[BN * NSLOT];
__device__ float g_p2v[BN * NSLOT];
__device__ int   g_p2i[BN * NSLOT];
__device__ float g_pm[BN * LNCH];
__device__ float g_ps[BN * LNCH];
__device__ float g_diag[BN];
__device__ int   g_ctr;

// ============================================================
// helpers
// ============================================================
__device__ __forceinline__ uint32_t smem_u32(const void* p) {
    uint32_t a;
    asm("{ .reg .u64 t; cvta.to.shared.u64 t, %1; cvt.u32.u64 %0, t; }" : "=r"(a) : "l"(p));
    return a;
}
__device__ __forceinline__ void cp16(uint32_t dst, const void* src) {
    asm volatile("cp.async.cg.shared.global [%0], [%1], 16;" :: "r"(dst), "l"(src));
}
#define CP_COMMIT() asm volatile("cp.async.commit_group;" ::: "memory")
#define CP_WAIT(n)  asm volatile("cp.async.wait_group %0;" :: "n"(n) : "memory")

#define LDSM4(r0, r1, r2, r3, addr)                                              \
    asm volatile("ldmatrix.sync.aligned.m8n8.x4.shared.b16 {%0,%1,%2,%3}, [%4];" \
        : "=r"(r0), "=r"(r1), "=r"(r2), "=r"(r3) : "r"(addr))

#define MMA16816(cc, aa, b0, b1)                                                 \
    asm volatile("mma.sync.aligned.m16n8k16.row.col.f32.bf16.bf16.f32 "          \
        "{%0,%1,%2,%3}, {%4,%5,%6,%7}, {%8,%9}, {%0,%1,%2,%3};"                  \
        : "+f"((cc)[0]), "+f"((cc)[1]), "+f"((cc)[2]), "+f"((cc)[3])             \
        : "r"((aa)[0]), "r"((aa)[1]), "r"((aa)[2]), "r"((aa)[3]), "r"(b0), "r"(b1))

__device__ __forceinline__ void top2_ins(float v, int i, float& v1, int& i1, float& v2, int& i2) {
    if (v > v1) { v2 = v1; i2 = i1; v1 = v; i1 = i; }
    else if (v > v2) { v2 = v; i2 = i; }
}

// ============================================================
// Stage 0: fused fp32->bf16 conversion: emb, queue, preds.
// Also resets the loss completion counter (graph-replay safe).
// ============================================================
#define NEMB8   (BN * D / 8)
#define NQ8     (QN * D / 8)
#define NPRED8  (BN * D / 8)
__global__ __launch_bounds__(256) void convert_all_kernel(
    const float* __restrict__ emb, const float* __restrict__ queue,
    const float* __restrict__ preds)
{
    int t = blockIdx.x * 256 + threadIdx.x;
    if (t == 0) g_ctr = 0;
    const float4* s;
    uint4* dstv;
    if (t < NEMB8) {
        s = (const float4*)emb + 2 * (size_t)t;
        dstv = (uint4*)g_emb_bf + t;
    } else if (t < NEMB8 + NQ8) {
        int j = t - NEMB8;
        s = (const float4*)queue + 2 * (size_t)j;
        dstv = (uint4*)g_queue_bf + j;
    } else if (t < NEMB8 + NQ8 + NPRED8) {
        int j = t - NEMB8 - NQ8;
        s = (const float4*)preds + 2 * (size_t)j;
        dstv = (uint4*)g_preds_bf + j;
    } else return;
    float4 a = s[0], b = s[1];
    uint32_t p0 = ((uint32_t)__bfloat16_as_ushort(__float2bfloat16(a.y)) << 16) |
                   (uint32_t)__bfloat16_as_ushort(__float2bfloat16(a.x));
    uint32_t p1 = ((uint32_t)__bfloat16_as_ushort(__float2bfloat16(a.w)) << 16) |
                   (uint32_t)__bfloat16_as_ushort(__float2bfloat16(a.z));
    uint32_t p2 = ((uint32_t)__bfloat16_as_ushort(__float2bfloat16(b.y)) << 16) |
                   (uint32_t)__bfloat16_as_ushort(__float2bfloat16(b.x));
    uint32_t p3 = ((uint32_t)__bfloat16_as_ushort(__float2bfloat16(b.w)) << 16) |
                   (uint32_t)__bfloat16_as_ushort(__float2bfloat16(b.z));
    *dstv = make_uint4(p0, p1, p2, p3);
}

// ============================================================
// Stage 1: bf16 mma.sync GEMM tile (128x128, K=256), 3-stage pipeline,
// one __syncthreads per k-chunk, top-2 epilogue in pipeline buffer 1.
// ============================================================
__global__ __launch_bounds__(256, 2) void sim_mma_kernel()
{
    extern __shared__ char smem[];
    const int tid  = threadIdx.x;
    const int lane = tid & 31, wid = tid >> 5;
    const int wm   = wid & 1, wn = wid >> 1;   // 2 x 4 warp layout
    const int bx   = blockIdx.x, by = blockIdx.y;

    const __nv_bfloat16* Ag = g_emb_bf   + (size_t)by * BM  * D;
    const __nv_bfloat16* Bg = g_queue_bf + (size_t)bx * BNT * D;

    const uint32_t sbase = smem_u32(smem);

    float c[4][4][4];
#pragma unroll
    for (int mi = 0; mi < 4; mi++)
#pragma unroll
        for (int ni = 0; ni < 4; ni++)
#pragma unroll
            for (int r = 0; r < 4; r++) c[mi][ni][r] = 0.0f;

    const uint32_t a_off = (uint32_t)(((wm * 64 + (lane & 15)) * PA + ((lane >> 4) << 3)) * 2);
    const uint32_t b_off = (uint32_t)(ABYTES +
        ((wn * 32 + (lane & 7) + ((lane >> 4) << 3)) * PA + (((lane >> 3) & 1) << 3)) * 2);

#define LOAD_STAGE(kc, buf) do {                                                  \
        uint32_t _ab = sbase + (buf) * STAGE_BYTES;                               \
        uint32_t _bb = _ab + ABYTES;                                              \
        _Pragma("unroll")                                                         \
        for (int _t = 0; _t < 4; _t++) {                                          \
            int _i = tid + _t * 256;                                              \
            int _r = _i >> 3, _c = _i & 7;                                        \
            cp16(_ab + (uint32_t)((_r * PA + _c * 8) * 2),                        \
                 Ag + (size_t)_r * D + (kc) * KC + _c * 8);                       \
            cp16(_bb + (uint32_t)((_r * PA + _c * 8) * 2),                        \
                 Bg + (size_t)_r * D + (kc) * KC + _c * 8);                       \
        }                                                                         \
        CP_COMMIT();                                                              \
    } while (0)

    LOAD_STAGE(0, 0);
    LOAD_STAGE(1, 1);

#pragma unroll
    for (int kc = 0; kc < NKC; kc++) {
        if (kc + 1 < NKC) { CP_WAIT(1); } else { CP_WAIT(0); }
        __syncthreads();                 // buffer kc ready; all done with buf being overwritten
        if (kc + 2 < NKC) LOAD_STAGE(kc + 2, (kc + 2) % 3);
        const uint32_t stage = sbase + (kc % 3) * STAGE_BYTES;
#pragma unroll
        for (int ks = 0; ks < KC / 16; ks++) {
            uint32_t a[4][4], b[4][2];
#pragma unroll
            for (int mi = 0; mi < 4; mi++)
                LDSM4(a[mi][0], a[mi][1], a[mi][2], a[mi][3],
                      stage + a_off + (uint32_t)((mi * 16 * PA + ks * 16) * 2));
#pragma unroll
            for (int nj = 0; nj < 2; nj++) {
                uint32_t r0, r1, r2, r3;
                LDSM4(r0, r1, r2, r3,
                      stage + b_off + (uint32_t)((nj * 16 * PA + ks * 16) * 2));
                b[nj * 2][0] = r0; b[nj * 2][1] = r1;
                b[nj * 2 + 1][0] = r2; b[nj * 2 + 1][1] = r3;
            }
#pragma unroll
            for (int mi = 0; mi < 4; mi++)
#pragma unroll
                for (int ni = 0; ni < 4; ni++)
                    MMA16816(c[mi][ni], a[mi], b[ni][0], b[ni][1]);
        }
    }
#undef LOAD_STAGE

    // ---- epilogue: per-row top-2 over this CTA's 128 cols ----
    float4* ep = (float4*)(smem + STAGE_BYTES);    // [128 rows][4 warp_n]
    const int g = lane >> 2, t4 = lane & 3;
    const int colb = bx * BNT + wn * 32 + t4 * 2;
#pragma unroll
    for (int mi = 0; mi < 4; mi++) {
#pragma unroll
        for (int h = 0; h < 2; h++) {
            float v1 = -3.0e38f, v2 = -3.0e38f;
            int i1 = 0, i2 = 0;
#pragma unroll
            for (int ni = 0; ni < 4; ni++) {
                top2_ins(c[mi][ni][h * 2],     colb + ni * 8,     v1, i1, v2, i2);
                top2_ins(c[mi][ni][h * 2 + 1], colb + ni * 8 + 1, v1, i1, v2, i2);
            }
#pragma unroll
            for (int off = 1; off <= 2; off <<= 1) {
                float ov1 = __shfl_xor_sync(0xffffffffu, v1, off);
                int   oi1 = __shfl_xor_sync(0xffffffffu, i1, off);
                float ov2 = __shfl_xor_sync(0xffffffffu, v2, off);
                int   oi2 = __shfl_xor_sync(0xffffffffu, i2, off);
                top2_ins(ov1, oi1, v1, i1, v2, i2);
                top2_ins(ov2, oi2, v1, i1, v2, i2);
            }
            if (t4 == 0) {
                int rin = wm * 64 + mi * 16 + h * 8 + g;
                ep[rin * 4 + wn] = make_float4(v1, __int_as_float(i1), v2, __int_as_float(i2));
            }
        }
    }
    __syncthreads();
    if (tid < BM) {
        float v1 = -3.0e38f, v2 = -3.0e38f;
        int i1 = 0, i2 = 0;
#pragma unroll
        for (int w = 0; w < 4; w++) {
            float4 e = ep[tid * 4 + w];
            top2_ins(e.x, __float_as_int(e.y), v1, i1, v2, i2);
            top2_ins(e.z, __float_as_int(e.w), v1, i1, v2, i2);
        }
        int row = by * BM + tid;
        g_p1v[(size_t)row * NSLOT + bx] = v1;
        g_p1i[(size_t)row * NSLOT + bx] = i1;
        g_p2v[(size_t)row * NSLOT + bx] = v2;
        g_p2i[(size_t)row * NSLOT + bx] = i2;
    }
}

// ============================================================
// Stage 2: fp32 rescore -> exact argmax; stores nearest row as bf16
// (straight copy from g_queue_bf — loss GEMM is plain bf16 now).
// ============================================================
__global__ __launch_bounds__(256) void rescore_kernel(
    const float* __restrict__ emb, const float* __restrict__ queue)
{
    const int warp = (blockIdx.x * 256 + threadIdx.x) >> 5;
    const int lane = threadIdx.x & 31;
    if (warp >= BN) return;
    const int row = warp;
    const size_t rb = (size_t)row * NSLOT;

    float m = -3.0e38f;
    for (int s = lane; s < NSLOT; s += 32) m = fmaxf(m, g_p1v[rb + s]);
#pragma unroll
    for (int off = 16; off; off >>= 1) m = fmaxf(m, __shfl_xor_sync(0xffffffffu, m, off));
    const float thr = m - EPS;

    const float4 e0 = *(const float4*)(emb + (size_t)row * D + lane * 8);
    const float4 e1 = *(const float4*)(emb + (size_t)row * D + lane * 8 + 4);

    float bestv = -3.0e38f;
    int besti = 0x7fffffff;
    for (int gnum = 0; gnum < NSLOT / 32; gnum++) {
        int e = gnum * 32 + lane;
        float v = g_p1v[rb + e];
        unsigned ball = __ballot_sync(0xffffffffu, v >= thr);
        while (ball) {
            int b = __ffs(ball) - 1;
            ball &= ball - 1;
            int slot = gnum * 32 + b;
            int ci = g_p1i[rb + slot];
            {
                const float4 q0 = *(const float4*)(queue + (size_t)ci * D + lane * 8);
                const float4 q1 = *(const float4*)(queue + (size_t)ci * D + lane * 8 + 4);
                float p = e0.x * q0.x + e0.y * q0.y + e0.z * q0.z + e0.w * q0.w
                        + e1.x * q1.x + e1.y * q1.y + e1.z * q1.z + e1.w * q1.w;
#pragma unroll
                for (int off = 16; off; off >>= 1) p += __shfl_xor_sync(0xffffffffu, p, off);
                if (p > bestv || (p == bestv && ci < besti)) { bestv = p; besti = ci; }
            }
            float v2 = g_p2v[rb + slot];
            if (v2 >= thr) {
                int ci2 = g_p2i[rb + slot];
                const float4 q0 = *(const float4*)(queue + (size_t)ci2 * D + lane * 8);
                const float4 q1 = *(const float4*)(queue + (size_t)ci2 * D + lane * 8 + 4);
                float p = e0.x * q0.x + e0.y * q0.y + e0.z * q0.z + e0.w * q0.w
                        + e1.x * q1.x + e1.y * q1.y + e1.z * q1.z + e1.w * q1.w;
#pragma unroll
                for (int off = 16; off; off >>= 1) p += __shfl_xor_sync(0xffffffffu, p, off);
                if (p > bestv || (p == bestv && ci2 < besti)) { bestv = p; besti = ci2; }
            }
        }
    }
    // copy queue[besti] (bf16) -> g_nn_bf[row] : 512B = 32 lanes x uint4
    const uint4 nv = ((const uint4*)(g_queue_bf + (size_t)besti * D))[lane];
    ((uint4*)(g_nn_bf + (size_t)row * D))[lane] = nv;
}

// ============================================================
// Stage 3: logits = nearest @ preds_opp^T / T via plain bf16 HMMA,
// 128x128 tiles, 256 thr, double-buffered kc, 2 CTAs/SM.
// Fused online LSE + diag + final reduction. Grid (16, 32) = 512 CTAs.
// ============================================================
__global__ __launch_bounds__(256, 2) void loss_mma_kernel(float* __restrict__ out)
{
    extern __shared__ char smem[];
    const int tid  = threadIdx.x;
    const int lane = tid & 31, wid = tid >> 5;
    const int wm   = wid & 1, wn = wid >> 1;   // 2 x 4
    const int bx   = blockIdx.x, by = blockIdx.y;
    const int row0 = by * BM;
    const int opp  = (row0 < HALF) ? HALF : 0;

    const __nv_bfloat16* Ag = g_nn_bf    + (size_t)row0 * D;
    const __nv_bfloat16* Bg = g_preds_bf + (size_t)(opp + bx * LBN) * D;

    const uint32_t sbase = smem_u32(smem);

    float c[4][4][4];
#pragma unroll
    for (int mi = 0; mi < 4; mi++)
#pragma unroll
        for (int ni = 0; ni < 4; ni++)
#pragma unroll
            for (int r = 0; r < 4; r++) c[mi][ni][r] = 0.0f;

    const uint32_t a_off = (uint32_t)(((wm * 64 + (lane & 15)) * PA + ((lane >> 4) << 3)) * 2);
    const uint32_t b_off = (uint32_t)(ABYTES +
        ((wn * 32 + (lane & 7) + ((lane >> 4) << 3)) * PA + (((lane >> 3) & 1) << 3)) * 2);

#define LLOAD(kc, buf) do {                                                       \
        uint32_t _ab = sbase + (buf) * LSTG;                                      \
        uint32_t _bb = _ab + ABYTES;                                              \
        _Pragma("unroll")                                                         \
        for (int _t = 0; _t < 4; _t++) {                                          \
            int _i = tid + _t * 256;                                              \
            int _r = _i >> 3, _c = _i & 7;                                        \
            cp16(_ab + (uint32_t)((_r * PA + _c * 8) * 2),                        \
                 Ag + (size_t)_r * D + (kc) * KC + _c * 8);                       \
            cp16(_bb + (uint32_t)((_r * PA + _c * 8) * 2),                        \
                 Bg + (size_t)_r * D + (kc) * KC + _c * 8);                       \
        }                                                                         \
        CP_COMMIT();                                                              \
    } while (0)

    LLOAD(0, 0);

    for (int kc = 0; kc < NKC; kc++) {
        if (kc + 1 < NKC) { LLOAD(kc + 1, (kc + 1) & 1); CP_WAIT(1); }
        else              { CP_WAIT(0); }
        __syncthreads();                       // chunk kc landed for everyone
        const uint32_t st = sbase + (kc & 1) * LSTG;
#pragma unroll
        for (int ks = 0; ks < KC / 16; ks++) {
            uint32_t a[4][4], b[4][2];
#pragma unroll
            for (int mi = 0; mi < 4; mi++)
                LDSM4(a[mi][0], a[mi][1], a[mi][2], a[mi][3],
                      st + a_off + (uint32_t)((mi * 16 * PA + ks * 16) * 2));
#pragma unroll
            for (int nj = 0; nj < 2; nj++) {
                uint32_t r0, r1, r2, r3;
                LDSM4(r0, r1, r2, r3,
                      st + b_off + (uint32_t)((nj * 16 * PA + ks * 16) * 2));
                b[nj * 2][0] = r0; b[nj * 2][1] = r1;
                b[nj * 2 + 1][0] = r2; b[nj * 2 + 1][1] = r3;
            }
#pragma unroll
            for (int mi = 0; mi < 4; mi++)
#pragma unroll
                for (int ni = 0; ni < 4; ni++)
                    MMA16816(c[mi][ni], a[mi], b[ni][0], b[ni][1]);
        }
        __syncthreads();                       // all warps done with buffer kc&1
    }
#undef LLOAD

    // ---- epilogue: scale, diag, online LSE over this CTA's 128 cols ----
    float2* part = (float2*)smem;        // [128 rows][4 warp_n]
    const int g = lane >> 2, t4 = lane & 3;
#pragma unroll
    for (int mi = 0; mi < 4; mi++) {
#pragma unroll
        for (int h = 0; h < 2; h++) {
            const int rin = wm * 64 + mi * 16 + h * 8 + g;
            const int row = row0 + rin;
            const int label = row & (HALF - 1);
            float m = -3.0e38f, s = 0.0f;
#pragma unroll
            for (int ni = 0; ni < 4; ni++) {
#pragma unroll
                for (int e = 0; e < 2; e++) {
                    float v = c[mi][ni][h * 2 + e] * TEMP_INV;
                    int col = bx * LBN + wn * 32 + ni * 8 + t4 * 2 + e;
                    if (col == label) g_diag[row] = v;
                    if (v > m) { s = s * expf(m - v) + 1.0f; m = v; }
                    else       { s += expf(v - m); }
                }
            }
#pragma unroll
            for (int off = 1; off <= 2; off <<= 1) {
                float om = __shfl_xor_sync(0xffffffffu, m, off);
                float os = __shfl_xor_sync(0xffffffffu, s, off);
                float M = fmaxf(m, om);
                s = s * expf(m - M) + os * expf(om - M);
                m = M;
            }
            if (t4 == 0) part[rin * 4 + wn] = make_float2(m, s);
        }
    }
    __syncthreads();
    if (tid < BM) {
        float M = -3.0e38f;
#pragma unroll
        for (int w = 0; w < 4; w++) M = fmaxf(M, part[tid * 4 + w].x);
        float S = 0.0f;
#pragma unroll
        for (int w = 0; w < 4; w++) {
            float2 p = part[tid * 4 + w];
            S += p.y * expf(p.x - M);
        }
        int row = row0 + tid;
        g_pm[row * LNCH + bx] = M;
        g_ps[row * LNCH + bx] = S;
    }

    // ---- fused final reduction: last CTA combines everything ----
    __syncthreads();
    __shared__ int s_last;
    if (tid == 0) {
        __threadfence();
        s_last = (atomicAdd(&g_ctr, 1) == LOSS_GRID - 1);
    }
    __syncthreads();
    if (!s_last) return;
    __threadfence();

    float* red = (float*)smem;
    float acc = 0.0f;
    for (int r = tid; r < BN; r += 256) {
        float M = -3.0e38f;
#pragma unroll
        for (int cc = 0; cc < LNCH; cc++) M = fmaxf(M, g_pm[r * LNCH + cc]);
        float S = 0.0f;
#pragma unroll
        for (int cc = 0; cc < LNCH; cc++) S += g_ps[r * LNCH + cc] * expf(g_pm[r * LNCH + cc] - M);
        acc += (logf(S) + M) - g_diag[r];
    }
    red[tid] = acc;
    __syncthreads();
    for (int st2 = 128; st2; st2 >>= 1) {
        if (tid < st2) red[tid] += red[tid + st2];
        __syncthreads();
    }
    if (tid == 0) out[0] = red[0] * (1.0f / (float)BN);
}

// ============================================================
extern "C" void kernel_launch(void* const* d_in, const int* in_sizes, int n_in,
                              void* d_out, int out_size)
{
    const float* emb   = (const float*)d_in[0];
    const float* preds = (const float*)d_in[1];
    const float* queue = (const float*)d_in[2];

    cudaFuncSetAttribute(sim_mma_kernel,
                         cudaFuncAttributeMaxDynamicSharedMemorySize, SIM_SMEM);
    cudaFuncSetAttribute(loss_mma_kernel,
                         cudaFuncAttributeMaxDynamicSharedMemorySize, LOSS_SMEM);

    convert_all_kernel<<<(NEMB8 + NQ8 + NPRED8 + 255) / 256, 256>>>(emb, queue, preds);
    sim_mma_kernel<<<dim3(QN / BNT, BN / BM), 256, SIM_SMEM>>>();
    rescore_kernel<<<BN / 8, 256>>>(emb, queue);
    loss_mma_kernel<<<dim3(LNCH, BN / BM), 256, LOSS_SMEM>>>((float*)d_out);
}

// round 16
// speedup vs baseline: 1.0372x; 1.0372x over previous
#include <cuda_runtime.h>
#include <cuda_bf16.h>
#include <math.h>
#include <stdint.h>

#define D       256
#define BN      4096
#define QN      65536
#define HALF    2048
#define TEMP_INV 10.0f

// ---- stage-1 mma.sync tiling: 128x128 tile, 256 thr, 3-stage pipeline ----
#define BM      128
#define BNT     128
#define KC      64
#define NKC     (D / KC)
#define PA      72                      // smem pitch (bf16): 144B rows, LDSM conflict-free
#define ABYTES  (BM * PA * 2)           // 18432
#define BBYTES  (BNT * PA * 2)          // 18432
#define STAGE_BYTES (ABYTES + BBYTES)   // 36864
#define SIM_SMEM    (3 * STAGE_BYTES)   // 110592 (2 CTAs/SM)

#define NSLOT   (QN / BNT)              // 512 partial-top2 slots per row
#define EPS     0.08f

// ---- stage-3 (plain bf16) tiling: 128x256 tiles, 512 thr, db kc ----
#define LBN     256
#define LNCH    (HALF / LBN)            // 8 col chunks
#define LBBYTES (LBN * PA * 2)          // 36864
#define LSTG    (ABYTES + LBBYTES)      // A + B chunk = 55296
#define LOSS_SMEM (2 * LSTG)            // 110592 (double-buffered)
#define LOSS_GRID (LNCH * (BN / BM))    // 256 CTAs

// ---- scratch (no allocations allowed) ----
__device__ __nv_bfloat16 g_emb_bf[BN * D];
__device__ __nv_bfloat16 g_queue_bf[QN * D];
__device__ __nv_bfloat16 g_preds_bf[BN * D];
__device__ __nv_bfloat16 g_nn_bf[BN * D];
__device__ float g_p1v[BN * NSLOT];
__device__ int   g_p1i[BN * NSLOT];
__device__ float g_p2v[BN * NSLOT];
__device__ int   g_p2i[BN * NSLOT];
__device__ float g_pm[BN * LNCH];
__device__ float g_ps[BN * LNCH];
__device__ float g_diag[BN];
__device__ int   g_ctr;

// ============================================================
// helpers
// ============================================================
__device__ __forceinline__ uint32_t smem_u32(const void* p) {
    uint32_t a;
    asm("{ .reg .u64 t; cvta.to.shared.u64 t, %1; cvt.u32.u64 %0, t; }" : "=r"(a) : "l"(p));
    return a;
}
__device__ __forceinline__ void cp16(uint32_t dst, const void* src) {
    asm volatile("cp.async.cg.shared.global [%0], [%1], 16;" :: "r"(dst), "l"(src));
}
#define CP_COMMIT() asm volatile("cp.async.commit_group;" ::: "memory")
#define CP_WAIT(n)  asm volatile("cp.async.wait_group %0;" :: "n"(n) : "memory")

#define LDSM4(r0, r1, r2, r3, addr)                                              \
    asm volatile("ldmatrix.sync.aligned.m8n8.x4.shared.b16 {%0,%1,%2,%3}, [%4];" \
        : "=r"(r0), "=r"(r1), "=r"(r2), "=r"(r3) : "r"(addr))

#define MMA16816(cc, aa, b0, b1)                                                 \
    asm volatile("mma.sync.aligned.m16n8k16.row.col.f32.bf16.bf16.f32 "          \
        "{%0,%1,%2,%3}, {%4,%5,%6,%7}, {%8,%9}, {%0,%1,%2,%3};"                  \
        : "+f"((cc)[0]), "+f"((cc)[1]), "+f"((cc)[2]), "+f"((cc)[3])             \
        : "r"((aa)[0]), "r"((aa)[1]), "r"((aa)[2]), "r"((aa)[3]), "r"(b0), "r"(b1))

__device__ __forceinline__ void top2_ins(float v, int i, float& v1, int& i1, float& v2, int& i2) {
    if (v > v1) { v2 = v1; i2 = i1; v1 = v; i1 = i; }
    else if (v > v2) { v2 = v; i2 = i; }
}

// ============================================================
// Stage 0: fused fp32->bf16 conversion: emb, queue, preds.
// Also resets the loss completion counter (graph-replay safe).
// ============================================================
#define NEMB8   (BN * D / 8)
#define NQ8     (QN * D / 8)
#define NPRED8  (BN * D / 8)
__global__ __launch_bounds__(256) void convert_all_kernel(
    const float* __restrict__ emb, const float* __restrict__ queue,
    const float* __restrict__ preds)
{
    int t = blockIdx.x * 256 + threadIdx.x;
    if (t == 0) g_ctr = 0;
    const float4* s;
    uint4* dstv;
    if (t < NEMB8) {
        s = (const float4*)emb + 2 * (size_t)t;
        dstv = (uint4*)g_emb_bf + t;
    } else if (t < NEMB8 + NQ8) {
        int j = t - NEMB8;
        s = (const float4*)queue + 2 * (size_t)j;
        dstv = (uint4*)g_queue_bf + j;
    } else if (t < NEMB8 + NQ8 + NPRED8) {
        int j = t - NEMB8 - NQ8;
        s = (const float4*)preds + 2 * (size_t)j;
        dstv = (uint4*)g_preds_bf + j;
    } else return;
    float4 a = s[0], b = s[1];
    uint32_t p0 = ((uint32_t)__bfloat16_as_ushort(__float2bfloat16(a.y)) << 16) |
                   (uint32_t)__bfloat16_as_ushort(__float2bfloat16(a.x));
    uint32_t p1 = ((uint32_t)__bfloat16_as_ushort(__float2bfloat16(a.w)) << 16) |
                   (uint32_t)__bfloat16_as_ushort(__float2bfloat16(a.z));
    uint32_t p2 = ((uint32_t)__bfloat16_as_ushort(__float2bfloat16(b.y)) << 16) |
                   (uint32_t)__bfloat16_as_ushort(__float2bfloat16(b.x));
    uint32_t p3 = ((uint32_t)__bfloat16_as_ushort(__float2bfloat16(b.w)) << 16) |
                   (uint32_t)__bfloat16_as_ushort(__float2bfloat16(b.z));
    *dstv = make_uint4(p0, p1, p2, p3);
}

// ============================================================
// Stage 1: bf16 mma.sync GEMM tile (128x128, K=256), 3-stage pipeline,
// one __syncthreads per k-chunk, top-2 epilogue in pipeline buffer 1.
// ============================================================
__global__ __launch_bounds__(256, 2) void sim_mma_kernel()
{
    extern __shared__ char smem[];
    const int tid  = threadIdx.x;
    const int lane = tid & 31, wid = tid >> 5;
    const int wm   = wid & 1, wn = wid >> 1;   // 2 x 4 warp layout
    const int bx   = blockIdx.x, by = blockIdx.y;

    const __nv_bfloat16* Ag = g_emb_bf   + (size_t)by * BM  * D;
    const __nv_bfloat16* Bg = g_queue_bf + (size_t)bx * BNT * D;

    const uint32_t sbase = smem_u32(smem);

    float c[4][4][4];
#pragma unroll
    for (int mi = 0; mi < 4; mi++)
#pragma unroll
        for (int ni = 0; ni < 4; ni++)
#pragma unroll
            for (int r = 0; r < 4; r++) c[mi][ni][r] = 0.0f;

    const uint32_t a_off = (uint32_t)(((wm * 64 + (lane & 15)) * PA + ((lane >> 4) << 3)) * 2);
    const uint32_t b_off = (uint32_t)(ABYTES +
        ((wn * 32 + (lane & 7) + ((lane >> 4) << 3)) * PA + (((lane >> 3) & 1) << 3)) * 2);

#define LOAD_STAGE(kc, buf) do {                                                  \
        uint32_t _ab = sbase + (buf) * STAGE_BYTES;                               \
        uint32_t _bb = _ab + ABYTES;                                              \
        _Pragma("unroll")                                                         \
        for (int _t = 0; _t < 4; _t++) {                                          \
            int _i = tid + _t * 256;                                              \
            int _r = _i >> 3, _c = _i & 7;                                        \
            cp16(_ab + (uint32_t)((_r * PA + _c * 8) * 2),                        \
                 Ag + (size_t)_r * D + (kc) * KC + _c * 8);                       \
            cp16(_bb + (uint32_t)((_r * PA + _c * 8) * 2),                        \
                 Bg + (size_t)_r * D + (kc) * KC + _c * 8);                       \
        }                                                                         \
        CP_COMMIT();                                                              \
    } while (0)

    LOAD_STAGE(0, 0);
    LOAD_STAGE(1, 1);

#pragma unroll
    for (int kc = 0; kc < NKC; kc++) {
        if (kc + 1 < NKC) { CP_WAIT(1); } else { CP_WAIT(0); }
        __syncthreads();                 // buffer kc ready; all done with buf being overwritten
        if (kc + 2 < NKC) LOAD_STAGE(kc + 2, (kc + 2) % 3);
        const uint32_t stage = sbase + (kc % 3) * STAGE_BYTES;
#pragma unroll
        for (int ks = 0; ks < KC / 16; ks++) {
            uint32_t a[4][4], b[4][2];
#pragma unroll
            for (int mi = 0; mi < 4; mi++)
                LDSM4(a[mi][0], a[mi][1], a[mi][2], a[mi][3],
                      stage + a_off + (uint32_t)((mi * 16 * PA + ks * 16) * 2));
#pragma unroll
            for (int nj = 0; nj < 2; nj++) {
                uint32_t r0, r1, r2, r3;
                LDSM4(r0, r1, r2, r3,
                      stage + b_off + (uint32_t)((nj * 16 * PA + ks * 16) * 2));
                b[nj * 2][0] = r0; b[nj * 2][1] = r1;
                b[nj * 2 + 1][0] = r2; b[nj * 2 + 1][1] = r3;
            }
#pragma unroll
            for (int mi = 0; mi < 4; mi++)
#pragma unroll
                for (int ni = 0; ni < 4; ni++)
                    MMA16816(c[mi][ni], a[mi], b[ni][0], b[ni][1]);
        }
    }
#undef LOAD_STAGE

    // ---- epilogue: per-row top-2 over this CTA's 128 cols ----
    float4* ep = (float4*)(smem + STAGE_BYTES);    // [128 rows][4 warp_n]
    const int g = lane >> 2, t4 = lane & 3;
    const int colb = bx * BNT + wn * 32 + t4 * 2;
#pragma unroll
    for (int mi = 0; mi < 4; mi++) {
#pragma unroll
        for (int h = 0; h < 2; h++) {
            float v1 = -3.0e38f, v2 = -3.0e38f;
            int i1 = 0, i2 = 0;
#pragma unroll
            for (int ni = 0; ni < 4; ni++) {
                top2_ins(c[mi][ni][h * 2],     colb + ni * 8,     v1, i1, v2, i2);
                top2_ins(c[mi][ni][h * 2 + 1], colb + ni * 8 + 1, v1, i1, v2, i2);
            }
#pragma unroll
            for (int off = 1; off <= 2; off <<= 1) {
                float ov1 = __shfl_xor_sync(0xffffffffu, v1, off);
                int   oi1 = __shfl_xor_sync(0xffffffffu, i1, off);
                float ov2 = __shfl_xor_sync(0xffffffffu, v2, off);
                int   oi2 = __shfl_xor_sync(0xffffffffu, i2, off);
                top2_ins(ov1, oi1, v1, i1, v2, i2);
                top2_ins(ov2, oi2, v1, i1, v2, i2);
            }
            if (t4 == 0) {
                int rin = wm * 64 + mi * 16 + h * 8 + g;
                ep[rin * 4 + wn] = make_float4(v1, __int_as_float(i1), v2, __int_as_float(i2));
            }
        }
    }
    __syncthreads();
    if (tid < BM) {
        float v1 = -3.0e38f, v2 = -3.0e38f;
        int i1 = 0, i2 = 0;
#pragma unroll
        for (int w = 0; w < 4; w++) {
            float4 e = ep[tid * 4 + w];
            top2_ins(e.x, __float_as_int(e.y), v1, i1, v2, i2);
            top2_ins(e.z, __float_as_int(e.w), v1, i1, v2, i2);
        }
        int row = by * BM + tid;
        g_p1v[(size_t)row * NSLOT + bx] = v1;
        g_p1i[(size_t)row * NSLOT + bx] = i1;
        g_p2v[(size_t)row * NSLOT + bx] = v2;
        g_p2i[(size_t)row * NSLOT + bx] = i2;
    }
}

// ============================================================
// Stage 2: fp32 rescore -> exact argmax; stores nearest row as bf16.
// Scans only p1v; touches p2v/p2i/p1i ONLY for flagged slots.
// ============================================================
__global__ __launch_bounds__(256) void rescore_kernel(
    const float* __restrict__ emb, const float* __restrict__ queue)
{
    const int warp = (blockIdx.x * 256 + threadIdx.x) >> 5;
    const int lane = threadIdx.x & 31;
    if (warp >= BN) return;
    const int row = warp;
    const size_t rb = (size_t)row * NSLOT;

    float m = -3.0e38f;
    for (int s = lane; s < NSLOT; s += 32) m = fmaxf(m, g_p1v[rb + s]);
#pragma unroll
    for (int off = 16; off; off >>= 1) m = fmaxf(m, __shfl_xor_sync(0xffffffffu, m, off));
    const float thr = m - EPS;

    const float4 e0 = *(const float4*)(emb + (size_t)row * D + lane * 8);
    const float4 e1 = *(const float4*)(emb + (size_t)row * D + lane * 8 + 4);

    float bestv = -3.0e38f;
    int besti = 0x7fffffff;
    for (int gnum = 0; gnum < NSLOT / 32; gnum++) {
        int e = gnum * 32 + lane;
        float v = g_p1v[rb + e];
        unsigned ball = __ballot_sync(0xffffffffu, v >= thr);
        while (ball) {
            int b = __ffs(ball) - 1;
            ball &= ball - 1;
            int slot = gnum * 32 + b;
            int ci = g_p1i[rb + slot];
            {
                const float4 q0 = *(const float4*)(queue + (size_t)ci * D + lane * 8);
                const float4 q1 = *(const float4*)(queue + (size_t)ci * D + lane * 8 + 4);
                float p = e0.x * q0.x + e0.y * q0.y + e0.z * q0.z + e0.w * q0.w
                        + e1.x * q1.x + e1.y * q1.y + e1.z * q1.z + e1.w * q1.w;
#pragma unroll
                for (int off = 16; off; off >>= 1) p += __shfl_xor_sync(0xffffffffu, p, off);
                if (p > bestv || (p == bestv && ci < besti)) { bestv = p; besti = ci; }
            }
            float v2 = g_p2v[rb + slot];
            if (v2 >= thr) {
                int ci2 = g_p2i[rb + slot];
                const float4 q0 = *(const float4*)(queue + (size_t)ci2 * D + lane * 8);
                const float4 q1 = *(const float4*)(queue + (size_t)ci2 * D + lane * 8 + 4);
                float p = e0.x * q0.x + e0.y * q0.y + e0.z * q0.z + e0.w * q0.w
                        + e1.x * q1.x + e1.y * q1.y + e1.z * q1.z + e1.w * q1.w;
#pragma unroll
                for (int off = 16; off; off >>= 1) p += __shfl_xor_sync(0xffffffffu, p, off);
                if (p > bestv || (p == bestv && ci2 < besti)) { bestv = p; besti = ci2; }
            }
        }
    }
    // copy queue[besti] (bf16) -> g_nn_bf[row] : 512B = 32 lanes x uint4
    const uint4 nv = ((const uint4*)(g_queue_bf + (size_t)besti * D))[lane];
    ((uint4*)(g_nn_bf + (size_t)row * D))[lane] = nv;
}

// ============================================================
// Stage 3: logits = nearest @ preds_opp^T / T via plain bf16 HMMA,
// 128x256 tiles, 512 threads, kc loop double-buffered (110.6KB smem).
// Fused online LSE + diag + final reduction. Grid (8, 32) = 256 CTAs.
// ============================================================
__global__ __launch_bounds__(512, 1) void loss_mma_kernel(float* __restrict__ out)
{
    extern __shared__ char smem[];
    const int tid  = threadIdx.x;
    const int lane = tid & 31, wid = tid >> 5;
    const int wm   = wid & 1, wn = wid >> 1;   // 2 x 8
    const int bx   = blockIdx.x, by = blockIdx.y;
    const int row0 = by * BM;
    const int opp  = (row0 < HALF) ? HALF : 0;

    const __nv_bfloat16* Ag = g_nn_bf    + (size_t)row0 * D;
    const __nv_bfloat16* Bg = g_preds_bf + (size_t)(opp + bx * LBN) * D;

    const uint32_t sbase = smem_u32(smem);

    float c[4][4][4];
#pragma unroll
    for (int mi = 0; mi < 4; mi++)
#pragma unroll
        for (int ni = 0; ni < 4; ni++)
#pragma unroll
            for (int r = 0; r < 4; r++) c[mi][ni][r] = 0.0f;

    const uint32_t a_off = (uint32_t)(((wm * 64 + (lane & 15)) * PA + ((lane >> 4) << 3)) * 2);
    const uint32_t b_off = (uint32_t)(ABYTES +
        ((wn * 32 + (lane & 7) + ((lane >> 4) << 3)) * PA + (((lane >> 3) & 1) << 3)) * 2);

#define LLOAD(kc, buf) do {                                                       \
        uint32_t _ab = sbase + (buf) * LSTG;                                      \
        uint32_t _bb = _ab + ABYTES;                                              \
        _Pragma("unroll")                                                         \
        for (int _t = 0; _t < 2; _t++) {                                          \
            int _i = tid + _t * 512;                                              \
            int _r = _i >> 3, _c = _i & 7;                                        \
            cp16(_ab + (uint32_t)((_r * PA + _c * 8) * 2),                        \
                 Ag + (size_t)_r * D + (kc) * KC + _c * 8);                       \
        }                                                                         \
        _Pragma("unroll")                                                         \
        for (int _t = 0; _t < 4; _t++) {                                          \
            int _i = tid + _t * 512;                                              \
            int _r = _i >> 3, _c = _i & 7;                                        \
            cp16(_bb + (uint32_t)((_r * PA + _c * 8) * 2),                        \
                 Bg + (size_t)_r * D + (kc) * KC + _c * 8);                       \
        }                                                                         \
        CP_COMMIT();                                                              \
    } while (0)

    LLOAD(0, 0);

    for (int kc = 0; kc < NKC; kc++) {
        if (kc + 1 < NKC) { LLOAD(kc + 1, (kc + 1) & 1); CP_WAIT(1); }
        else              { CP_WAIT(0); }
        __syncthreads();                       // chunk kc landed for everyone
        const uint32_t st = sbase + (kc & 1) * LSTG;
#pragma unroll
        for (int ks = 0; ks < KC / 16; ks++) {
            uint32_t a[4][4], b[4][2];
#pragma unroll
            for (int mi = 0; mi < 4; mi++)
                LDSM4(a[mi][0], a[mi][1], a[mi][2], a[mi][3],
                      st + a_off + (uint32_t)((mi * 16 * PA + ks * 16) * 2));
#pragma unroll
            for (int nj = 0; nj < 2; nj++) {
                uint32_t r0, r1, r2, r3;
                LDSM4(r0, r1, r2, r3,
                      st + b_off + (uint32_t)((nj * 16 * PA + ks * 16) * 2));
                b[nj * 2][0] = r0; b[nj * 2][1] = r1;
                b[nj * 2 + 1][0] = r2; b[nj * 2 + 1][1] = r3;
            }
#pragma unroll
            for (int mi = 0; mi < 4; mi++)
#pragma unroll
                for (int ni = 0; ni < 4; ni++)
                    MMA16816(c[mi][ni], a[mi], b[ni][0], b[ni][1]);
        }
        __syncthreads();                       // all warps done with buffer kc&1
    }
#undef LLOAD

    // ---- epilogue: scale, diag, online LSE over this CTA's 256 cols ----
    float2* part = (float2*)smem;        // [128 rows][8 warp_n]
    const int g = lane >> 2, t4 = lane & 3;
#pragma unroll
    for (int mi = 0; mi < 4; mi++) {
#pragma unroll
        for (int h = 0; h < 2; h++) {
            const int rin = wm * 64 + mi * 16 + h * 8 + g;
            const int row = row0 + rin;
            const int label = row & (HALF - 1);
            float m = -3.0e38f, s = 0.0f;
#pragma unroll
            for (int ni = 0; ni < 4; ni++) {
#pragma unroll
                for (int e = 0; e < 2; e++) {
                    float v = c[mi][ni][h * 2 + e] * TEMP_INV;
                    int col = bx * LBN + wn * 32 + ni * 8 + t4 * 2 + e;
                    if (col == label) g_diag[row] = v;
                    if (v > m) { s = s * expf(m - v) + 1.0f; m = v; }
                    else       { s += expf(v - m); }
                }
            }
#pragma unroll
            for (int off = 1; off <= 2; off <<= 1) {
                float om = __shfl_xor_sync(0xffffffffu, m, off);
                float os = __shfl_xor_sync(0xffffffffu, s, off);
                float M = fmaxf(m, om);
                s = s * expf(m - M) + os * expf(om - M);
                m = M;
            }
            if (t4 == 0) part[rin * 8 + wn] = make_float2(m, s);
        }
    }
    __syncthreads();
    if (tid < BM) {
        float M = -3.0e38f;
#pragma unroll
        for (int w = 0; w < 8; w++) M = fmaxf(M, part[tid * 8 + w].x);
        float S = 0.0f;
#pragma unroll
        for (int w = 0; w < 8; w++) {
            float2 p = part[tid * 8 + w];
            S += p.y * expf(p.x - M);
        }
        int row = row0 + tid;
        g_pm[row * LNCH + bx] = M;
        g_ps[row * LNCH + bx] = S;
    }

    // ---- fused final reduction: last CTA combines everything ----
    __syncthreads();
    __shared__ int s_last;
    if (tid == 0) {
        __threadfence();
        s_last = (atomicAdd(&g_ctr, 1) == LOSS_GRID - 1);
    }
    __syncthreads();
    if (!s_last) return;
    __threadfence();

    float* red = (float*)smem;
    float acc = 0.0f;
    for (int r = tid; r < BN; r += 512) {
        float M = -3.0e38f;
#pragma unroll
        for (int cc = 0; cc < LNCH; cc++) M = fmaxf(M, g_pm[r * LNCH + cc]);
        float S = 0.0f;
#pragma unroll
        for (int cc = 0; cc < LNCH; cc++) S += g_ps[r * LNCH + cc] * expf(g_pm[r * LNCH + cc] - M);
        acc += (logf(S) + M) - g_diag[r];
    }
    red[tid] = acc;
    __syncthreads();
    for (int st2 = 256; st2; st2 >>= 1) {
        if (tid < st2) red[tid] += red[tid + st2];
        __syncthreads();
    }
    if (tid == 0) out[0] = red[0] * (1.0f / (float)BN);
}

// ============================================================
extern "C" void kernel_launch(void* const* d_in, const int* in_sizes, int n_in,
                              void* d_out, int out_size)
{
    const float* emb   = (const float*)d_in[0];
    const float* preds = (const float*)d_in[1];
    const float* queue = (const float*)d_in[2];

    cudaFuncSetAttribute(sim_mma_kernel,
                         cudaFuncAttributeMaxDynamicSharedMemorySize, SIM_SMEM);
    cudaFuncSetAttribute(loss_mma_kernel,
                         cudaFuncAttributeMaxDynamicSharedMemorySize, LOSS_SMEM);

    convert_all_kernel<<<(NEMB8 + NQ8 + NPRED8 + 255) / 256, 256>>>(emb, queue, preds);
    sim_mma_kernel<<<dim3(QN / BNT, BN / BM), 256, SIM_SMEM>>>();
    rescore_kernel<<<BN / 8, 256>>>(emb, queue);
    loss_mma_kernel<<<dim3(LNCH, BN / BM), 512, LOSS_SMEM>>>((float*)d_out);
}